// round 13
// baseline (speedup 1.0000x reference)
#include <cuda_runtime.h>
#include <cstdint>
#include <cstddef>

// RNN_49297634623576: out = fc_w @ tanh(w_ih @ x[:,27,:] + b_ih + b_hh) + fc_b
// hx == 0 => w_hh unused.
//
// R13 vs R12: per-j critical path was ~100 cyc (14 serial FFMA2 + hsum +
// tanh) carrying only ~33 issues -> per-warp duty 0.33, and lockstep warps
// bunch per-region (all in MUFU together, then all in FMA) -> issue 40%.
// Fix: process 2 j's per iteration in each half -> 2 independent layer-1
// chains, 2 parallel tanh, 10-target FC block. Duty ~0.6/warp. LDCU weight
// loads go to uniform regs (no warp-reg cost) so 7 CTAs/SM is preserved.
// Kept from R12: single memcpy graph node, warp-split halves, smem FC/bias.

#define NB   65536
#define NIN  28
#define NHID 64
#define NOUT 10
#define TPB  128   // 4 warps: (half, rowgroup); 64 rows/CTA -> 1024 CTAs

typedef unsigned long long u64;

__constant__ u64 c_w64[NHID * NIN / 2];  // raw w_ih: [j][p] = {w[j][2p], w[j][2p+1]}

__device__ __forceinline__ u64 pk2(float a, float b) {
    u64 r; asm("mov.b64 %0,{%1,%2};" : "=l"(r) : "f"(a), "f"(b)); return r;
}
__device__ __forceinline__ void upk2(u64 v, float& a, float& b) {
    asm("mov.b64 {%0,%1},%2;" : "=f"(a), "=f"(b) : "l"(v));
}
__device__ __forceinline__ u64 ffma2(u64 a, u64 b, u64 c) {
    u64 d; asm("fma.rn.f32x2 %0,%1,%2,%3;" : "=l"(d) : "l"(a), "l"(b), "l"(c)); return d;
}
__device__ __forceinline__ u64 fadd2(u64 a, u64 b) {
    u64 d; asm("add.rn.f32x2 %0,%1,%2;" : "=l"(d) : "l"(a), "l"(b)); return d;
}
__device__ __forceinline__ float hsum2(u64 v) {
    float a, b; upk2(v, a, b); return a + b;
}

// tanh(x) = 1 - 2*rcp(exp2(x*2log2e)+1); ~1e-6 accurate.
__device__ __forceinline__ float tanh_fast(float x) {
    const float LOG2E_X2 = 2.8853900817779268f;
    float e, r;
    asm("ex2.approx.ftz.f32 %0, %1;" : "=f"(e) : "f"(x * LOG2E_X2));
    asm("rcp.approx.ftz.f32 %0, %1;" : "=f"(r) : "f"(e + 1.0f));
    return fmaf(-2.0f, r, 1.0f);
}

// One half's work: 32 hidden units [JBASE, JBASE+32), 2 j per iteration.
// Fully unrolled: every c_w64 access is an immediate -> uniform-port LDCU.
template <int JBASE>
__device__ __forceinline__ void half_work(const u64 (&in)[NIN / 2],
                                          const u64* s_bp,
                                          const u64 (*s_fck)[6],
                                          u64 (&oa)[NOUT / 2])
{
#pragma unroll
    for (int jj = 0; jj < 32; jj += 2) {
        const int j0 = JBASE + jj, j1 = j0 + 1;

        // Two independent layer-1 chains (biases seeded from smem broadcast).
        u64 a0 = s_bp[j0];
        u64 a1 = s_bp[j1];
#pragma unroll
        for (int p = 0; p < NIN / 2; p++) {
            a0 = ffma2(c_w64[j0 * (NIN / 2) + p], in[p], a0);
            a1 = ffma2(c_w64[j1 * (NIN / 2) + p], in[p], a1);
        }

        // Two parallel tanh chains.
        float h0 = tanh_fast(hsum2(a0));
        float h1 = tanh_fast(hsum2(a1));
        u64 hp0 = pk2(h0, h0);
        u64 hp1 = pk2(h1, h1);

        // FC: 10 independent accumulator targets across the two j's.
        const ulonglong2* fr0 = reinterpret_cast<const ulonglong2*>(&s_fck[j0][0]);
        const ulonglong2* fr1 = reinterpret_cast<const ulonglong2*>(&s_fck[j1][0]);
        ulonglong2 fA = fr0[0], fB = fr0[1];
        ulonglong2 fC = fr1[0], fD = fr1[1];
        u64 fE = s_fck[j0][4], fF = s_fck[j1][4];
        oa[0] = ffma2(fA.x, hp0, oa[0]);
        oa[1] = ffma2(fA.y, hp0, oa[1]);
        oa[2] = ffma2(fB.x, hp0, oa[2]);
        oa[3] = ffma2(fB.y, hp0, oa[3]);
        oa[4] = ffma2(fE,   hp0, oa[4]);
        oa[0] = ffma2(fC.x, hp1, oa[0]);
        oa[1] = ffma2(fC.y, hp1, oa[1]);
        oa[2] = ffma2(fD.x, hp1, oa[2]);
        oa[3] = ffma2(fD.y, hp1, oa[3]);
        oa[4] = ffma2(fF,   hp1, oa[4]);
    }
}

__global__ void __launch_bounds__(TPB, 7)
rnn_fused_kernel(const float* __restrict__ x,
                 const float* __restrict__ b_ih,
                 const float* __restrict__ b_hh,
                 const float* __restrict__ fc_w,
                 const float* __restrict__ fc_b,
                 float* __restrict__ out)
{
    // FC weights on smem port: [j][q<5] = {fc_w[2q][j], fc_w[2q+1][j]}.
    __shared__ u64 s_fck[NHID][6];
    __shared__ u64 s_bp[NHID];          // {b_ih[j]+b_hh[j], 0}
    __shared__ u64 s_fcb[NOUT / 2];
    // Half-0 partials: [component][row_local]; 8B lane stride -> conflict-free.
    __shared__ u64 s_part[NOUT / 2][64];

    const int tid = threadIdx.x;

    for (int i = tid; i < NHID * (NOUT / 2); i += TPB) {
        int j = i / (NOUT / 2), q = i % (NOUT / 2);
        s_fck[j][q] = pk2(fc_w[(2 * q) * NHID + j], fc_w[(2 * q + 1) * NHID + j]);
    }
    for (int i = tid; i < NHID; i += TPB) {
        s_fck[i][5] = 0ull;
        s_bp[i] = pk2(b_ih[i] + b_hh[i], 0.0f);
    }
    if (tid < NOUT / 2) s_fcb[tid] = pk2(fc_b[2 * tid], fc_b[2 * tid + 1]);
    __syncthreads();

    const int wid  = tid >> 5;
    const int lane = tid & 31;
    const int half = wid & 1;                    // which 32 hidden units
    const int rloc = ((wid >> 1) << 5) + lane;   // row within CTA (0..63)
    const int row  = (blockIdx.x << 6) + rloc;

    // Last 28 floats of this row; float offset 756 is 16B aligned.
    u64 in[NIN / 2];
    {
        const float4* p = reinterpret_cast<const float4*>(x + (size_t)row * 784 + 756);
#pragma unroll
        for (int q = 0; q < 7; q++) {
            float4 v = p[q];
            in[2 * q]     = pk2(v.x, v.y);
            in[2 * q + 1] = pk2(v.z, v.w);
        }
    }

    u64 oa[NOUT / 2];
#pragma unroll
    for (int q = 0; q < NOUT / 2; q++) oa[q] = 0ull;

    // Warp-uniform branch: each instantiation has immediate const addresses.
    if (half == 0) half_work<0>(in, s_bp, s_fck, oa);
    else           half_work<32>(in, s_bp, s_fck, oa);

    // Half 0 publishes partials; half 1 combines (+ fc bias) and stores.
    if (half == 0) {
#pragma unroll
        for (int q = 0; q < NOUT / 2; q++) s_part[q][rloc] = oa[q];
    }
    __syncthreads();
    if (half == 1) {
        float2* o2 = reinterpret_cast<float2*>(out + (size_t)row * NOUT);
#pragma unroll
        for (int q = 0; q < NOUT / 2; q++) {
            u64 v = fadd2(fadd2(oa[q], s_part[q][rloc]), s_fcb[q]);
            float a, b;
            upk2(v, a, b);
            o2[q] = make_float2(a, b);
        }
    }
}

extern "C" void kernel_launch(void* const* d_in, const int* in_sizes, int n_in,
                              void* d_out, int out_size)
{
    (void)in_sizes; (void)n_in; (void)out_size;
    const float* x    = (const float*)d_in[0];
    // d_in[2] = w_hh : unused (hx == 0)
    const float* b_ih = (const float*)d_in[3];
    const float* b_hh = (const float*)d_in[4];
    const float* fc_w = (const float*)d_in[5];
    const float* fc_b = (const float*)d_in[6];
    float* out = (float*)d_out;

    // Single staging memcpy: w_ih -> constant (LDCU path). Async D2D,
    // graph-capturable, alloc-free, ordered before the kernel.
    cudaMemcpyToSymbolAsync(c_w64, d_in[1], NHID * NIN * sizeof(float), 0,
                            cudaMemcpyDeviceToDevice, 0);

    const int blocks = NB / 64;   // 1024, exact
    rnn_fused_kernel<<<blocks, TPB>>>(x, b_ih, b_hh, fc_w, fc_b, out);
}